// round 9
// baseline (speedup 1.0000x reference)
#include <cuda_runtime.h>
#include <math.h>

#define BB    256
#define T2V   1026
#define TP1   1025
#define SSV   1024
#define NVOC  35
#define H7    224
#define HN    (BB*SSV)
#define EPSV  2.220446049250313e-16f
#define LOG2E 1.4426950408889634f
#define LN2   0.6931471805599453f
#define FULLM 0xffffffffu

// ---------------- device scratch ----------------
static __device__ float g_prex[NVOC * H7];
static __device__ float g_c [BB * TP1 * 32];
static __device__ float g_cb[BB * TP1 * 32];
static __device__ float g_d [BB * TP1 * 32];   // delta in log2 domain
static __device__ float g_o [BB * TP1 * 32];
static __device__ float g_h [BB * TP1 * 32];
static __device__ float g_loglam[BB], g_nev[BB], g_integ[BB];

// ---------------- fast math ----------------
__device__ __forceinline__ float ex2f(float x){ float r; asm("ex2.approx.f32 %0,%1;":"=f"(r):"f"(x)); return r; }
__device__ __forceinline__ float lg2f(float x){ float r; asm("lg2.approx.f32 %0,%1;":"=f"(r):"f"(x)); return r; }
__device__ __forceinline__ float rcpf(float x){ float r; asm("rcp.approx.f32 %0,%1;":"=f"(r):"f"(x)); return r; }
__device__ __forceinline__ float sig_fast(float x){
    float s = ex2f(-fabsf(x) * LOG2E);
    float r = rcpf(1.0f + s);
    return x >= 0.0f ? r : s * r;
}
__device__ __forceinline__ float tanh_fast(float x){
    float s2 = ex2f(-2.0f * LOG2E * fabsf(x));
    float tv = (1.0f - s2) * rcpf(1.0f + s2);
    return x >= 0.0f ? tv : -tv;
}
__device__ __forceinline__ float softplus_fast(float x){
    return fmaxf(x, 0.0f) + lg2f(1.0f + ex2f(-fabsf(x) * LOG2E)) * LN2;
}
__device__ __forceinline__ float softplus_log2(float x){   // softplus(x)/ln2
    return fmaxf(x, 0.0f) * LOG2E + lg2f(1.0f + ex2f(-fabsf(x) * LOG2E));
}
__device__ __forceinline__ unsigned su32(const void* p){
    unsigned a;
    asm("{ .reg .u64 t; cvta.to.shared.u64 t, %1; cvt.u32.u64 %0, t; }" : "=r"(a) : "l"(p));
    return a;
}

// block reduction (result valid on thread 0); blockDim = 256
__device__ __forceinline__ float block_reduce(float v, float* sh) {
    #pragma unroll
    for (int o = 16; o > 0; o >>= 1) v += __shfl_down_sync(FULLM, v, o);
    int wid = threadIdx.x >> 5, lid = threadIdx.x & 31;
    if (lid == 0) sh[wid] = v;
    __syncthreads();
    if (wid == 0) {
        v = (lid < 8) ? sh[lid] : 0.0f;
        #pragma unroll
        for (int o = 4; o > 0; o >>= 1) v += __shfl_down_sync(FULLM, v, o);
    }
    return v;
}

// ---------------- kernel A: prex[v][j] = Emb[v]·Wx[:,j] + b[j] -------------
__global__ void k_prex(const float* __restrict__ Emb,
                       const float* __restrict__ W,
                       const float* __restrict__ bias) {
    int v = blockIdx.x;
    int j = threadIdx.x;
    float acc = bias[j];
    #pragma unroll
    for (int k = 0; k < 32; k++)
        acc += Emb[v * 32 + k] * W[k * H7 + j];
    g_prex[v * H7 + j] = acc;
}

// ---------------- kernel B: scan, TWO batches per CTA, packed f32x2 dots ---
// thread j (0..223) = gate (j>>5) of unit (j&31); uniform activation per warp.
// phase2: warp0 updates batch A, warp1 updates batch B.
__global__ void __launch_bounds__(224, 1)
k_scan(const int*   __restrict__ event,
       const float* __restrict__ dtime,
       const float* __restrict__ W) {
    const int cb   = blockIdx.x;            // 0..127
    const int b0   = 2 * cb, b1 = 2 * cb + 1;
    const int j    = threadIdx.x;
    const int w    = j >> 5;
    const int lane = j & 31;

    __shared__ float  prex_sh[NVOC * H7];   // 31.4 KB
    __shared__ float  act[2][H7];
    __shared__ float  e_sh[2][32];
    __shared__ float2 h2s[2][16];           // h vectors, float2-aligned
    __shared__ float  dt_sh[2][T2V];
    __shared__ int    ev_sh[2][T2V];

    for (int i = j; i < NVOC * H7; i += 224) prex_sh[i] = g_prex[i];
    for (int i = j; i < T2V; i += 224) {
        dt_sh[0][i] = dtime[b0 * T2V + i];
        dt_sh[1][i] = dtime[b1 * T2V + i];
        ev_sh[0][i] = event[b0 * T2V + i];
        ev_sh[1][i] = event[b1 * T2V + i];
    }

    // packed recurrent weight column: wp[k] = (W_h[2k][j], W_h[2k+1][j])
    unsigned long long wp[16];
    #pragma unroll
    for (int k = 0; k < 16; k++) {
        float wlo = W[(32 + 2 * k)     * H7 + j];
        float whi = W[(32 + 2 * k + 1) * H7 + j];
        asm("mov.b64 %0, {%1,%2};" : "=l"(wp[k]) : "f"(wlo), "f"(whi));
    }

    if (j < 64) ((float*)h2s)[j] = 0.0f;
    float cm = 0.0f, cbm = 0.0f;            // carries: warp0→A, warp1→B

    const unsigned hbA = su32(&h2s[0][0]);
    const unsigned hbB = su32(&h2s[1][0]);

    float* outcA  = g_c  + b0 * TP1 * 32;  float* outcB  = g_c  + b1 * TP1 * 32;
    float* outcbA = g_cb + b0 * TP1 * 32;  float* outcbB = g_cb + b1 * TP1 * 32;
    float* outdA  = g_d  + b0 * TP1 * 32;  float* outdB  = g_d  + b1 * TP1 * 32;
    float* outoA  = g_o  + b0 * TP1 * 32;  float* outoB  = g_o  + b1 * TP1 * 32;
    float* outhA  = g_h  + b0 * TP1 * 32;  float* outhB  = g_h  + b1 * TP1 * 32;

    __syncthreads();

    float pxA = prex_sh[ev_sh[0][0] * H7 + j];
    float pxB = prex_sh[ev_sh[1][0] * H7 + j];

    for (int t = 0; t < TP1; t++) {
        // ---------- phase 1: two packed dots + uniform activation ----------
        unsigned long long accA[4] = {0,0,0,0}, accB[4] = {0,0,0,0};
        #pragma unroll
        for (int k = 0; k < 16; k++) {
            unsigned long long hA, hB;
            asm volatile("ld.shared.b64 %0,[%1];" : "=l"(hA) : "r"(hbA + k * 8));
            asm volatile("ld.shared.b64 %0,[%1];" : "=l"(hB) : "r"(hbB + k * 8));
            asm volatile("fma.rn.f32x2 %0,%1,%2,%0;" : "+l"(accA[k & 3]) : "l"(hA), "l"(wp[k]));
            asm volatile("fma.rn.f32x2 %0,%1,%2,%0;" : "+l"(accB[k & 3]) : "l"(hB), "l"(wp[k]));
        }
        asm("add.rn.f32x2 %0,%0,%1;" : "+l"(accA[0]) : "l"(accA[1]));
        asm("add.rn.f32x2 %0,%0,%1;" : "+l"(accA[2]) : "l"(accA[3]));
        asm("add.rn.f32x2 %0,%0,%1;" : "+l"(accA[0]) : "l"(accA[2]));
        asm("add.rn.f32x2 %0,%0,%1;" : "+l"(accB[0]) : "l"(accB[1]));
        asm("add.rn.f32x2 %0,%0,%1;" : "+l"(accB[2]) : "l"(accB[3]));
        asm("add.rn.f32x2 %0,%0,%1;" : "+l"(accB[0]) : "l"(accB[2]));
        float loA, hiA, loB, hiB;
        asm("mov.b64 {%0,%1},%2;" : "=f"(loA), "=f"(hiA) : "l"(accA[0]));
        asm("mov.b64 {%0,%1},%2;" : "=f"(loB), "=f"(hiB) : "l"(accB[0]));
        float preA = pxA + loA + hiA;
        float preB = pxB + loB + hiB;

        float aA, aB;
        if (w == 2) {                       // z: tanh  (uniform per warp)
            aA = tanh_fast(preA); aB = tanh_fast(preB);
        } else if (w == 6) {                // delta: softplus in log2 domain
            aA = softplus_log2(preA); aB = softplus_log2(preB);
            e_sh[0][lane] = ex2f(-aA * dt_sh[0][t + 1]);
            e_sh[1][lane] = ex2f(-aB * dt_sh[1][t + 1]);
            outdA[t * 32 + lane] = aA;
            outdB[t * 32 + lane] = aB;
        } else {                            // i,f,o,ib,fb: sigmoid
            aA = sig_fast(preA); aB = sig_fast(preB);
            if (w == 3) {                   // o gate also goes to global
                outoA[t * 32 + lane] = aA;
                outoB[t * 32 + lane] = aB;
            }
        }
        act[0][j] = aA;
        act[1][j] = aB;

        // prefetch next step's pre-x (hidden under barrier + phase 2)
        if (t + 1 < TP1) {
            pxA = prex_sh[ev_sh[0][t + 1] * H7 + j];
            pxB = prex_sh[ev_sh[1][t + 1] * H7 + j];
        }
        __syncthreads();

        // ---------- phase 2: warp0 -> batch A, warp1 -> batch B ------------
        if (w < 2) {
            const float* A = act[w];
            float iv  = A[lane];
            float fv  = A[32  + lane];
            float zv  = A[64  + lane];
            float ov  = A[96  + lane];
            float ibv = A[128 + lane];
            float fbv = A[160 + lane];
            float e   = e_sh[w][lane];

            float c  = fmaf(fv,  cm,  iv  * zv);
            float cbv= fmaf(fbv, cbm, ibv * zv);
            float cn = fmaf(c - cbv, e, cbv);
            float h  = ov * tanh_fast(cn);

            int base = t * 32 + lane;
            if (w == 0) { outcA[base] = c; outcbA[base] = cbv; outhA[base] = h; }
            else        { outcB[base] = c; outcbB[base] = cbv; outhB[base] = h; }

            ((float*)h2s)[32 * w + lane] = h;
            cm = cn; cbm = cbv;
        }
        __syncthreads();
    }
}

// ---------------- kernel C: MC sampling + lambda_sample + integral ---------
__global__ void __launch_bounds__(256)
k_sample(const float* __restrict__ dts,
         const float* __restrict__ mask,
         const float* __restrict__ dur,
         const float* __restrict__ Wl,
         float* __restrict__ lam_out) {
    const int b    = blockIdx.x;
    const int tid  = threadIdx.x;
    const int lane = tid & 31;
    const int wid  = tid >> 5;

    __shared__ float sh_ch[8][32];
    __shared__ float red[8];

    float wle[32];
    const float4* wl4 = (const float4*)(Wl + lane * 32);
    #pragma unroll
    for (int p = 0; p < 8; p++) {
        float4 wv = wl4[p];
        wle[4 * p + 0] = wv.x; wle[4 * p + 1] = wv.y;
        wle[4 * p + 2] = wv.z; wle[4 * p + 3] = wv.w;
    }

    float accLam = 0.0f, accMask = 0.0f;

    for (int s = wid; s < SSV; s += 8) {
        int r    = b * SSV + s;
        int base = r * 32;

        float cv  = g_c [base + lane];
        float cbv = g_cb[base + lane];
        float dv  = g_d [base + lane];    // log2-domain delta
        float ov  = g_o [base + lane];
        float dtv = dts[r];

        float cd  = fmaf(cv - cbv, ex2f(-dv * dtv), cbv);
        float chv = ov * tanh_fast(cd);
        sh_ch[wid][lane] = chv;
        __syncwarp();

        float d0 = 0.f, d1 = 0.f, d2 = 0.f, d3 = 0.f;
        const float4* ch4 = (const float4*)sh_ch[wid];
        #pragma unroll
        for (int p = 0; p < 8; p++) {
            float4 c4 = ch4[p];
            d0 = fmaf(c4.x, wle[4 * p + 0], d0);
            d1 = fmaf(c4.y, wle[4 * p + 1], d1);
            d2 = fmaf(c4.z, wle[4 * p + 2], d2);
            d3 = fmaf(c4.w, wle[4 * p + 3], d3);
        }
        float sp = softplus_fast((d0 + d1) + (d2 + d3));
        lam_out[(size_t)r * 32 + lane] = sp;

        float m = mask[r];
        accLam += sp * m;
        if (lane == 0) accMask += m;
        __syncwarp();
    }

    float sLam = block_reduce(accLam, red);
    __syncthreads();
    float sMask = block_reduce(accMask, red);
    if (tid == 0) g_integ[b] = __fdividef(sLam, sMask) * dur[b];
}

// ---------------- kernel D: target log-lambda ------------------------------
__global__ void __launch_bounds__(256)
k_target(const int* __restrict__ event,
         const float* __restrict__ Wl) {
    const int b   = blockIdx.x;
    const int tid = threadIdx.x;

    __shared__ float wl[32 * 33];              // stride 33: conflict-free
    __shared__ float red[8];
    for (int i = tid; i < 1024; i += 256)
        wl[(i >> 5) * 33 + (i & 31)] = Wl[i];
    __syncthreads();

    const int* evrow = event + b * T2V;
    float accL = 0.0f, accN = 0.0f;

    for (int t = tid; t < TP1; t += 256) {
        int tgt = evrow[t + 1];
        bool m  = (tgt < 32);
        int tt  = m ? tgt : 0;

        const float4* h4 = (const float4*)(g_h + (b * TP1 + t) * 32);
        const float* wr  = wl + tt * 33;
        float d0 = 0.f, d1 = 0.f, d2 = 0.f, d3 = 0.f;
        #pragma unroll
        for (int p = 0; p < 8; p++) {
            float4 hv = h4[p];
            d0 = fmaf(hv.x, wr[4 * p + 0], d0);
            d1 = fmaf(hv.y, wr[4 * p + 1], d1);
            d2 = fmaf(hv.z, wr[4 * p + 2], d2);
            d3 = fmaf(hv.w, wr[4 * p + 3], d3);
        }
        float lam = softplus_fast((d0 + d1) + (d2 + d3));
        if (m) { accL += lg2f(lam + EPSV) * LN2; accN += 1.0f; }
    }

    float sL = block_reduce(accL, red);
    __syncthreads();
    float sN = block_reduce(accN, red);
    if (tid == 0) { g_loglam[b] = sL; g_nev[b] = sN; }
}

// ---------------- kernel E: final scalars ----------------------------------
__global__ void __launch_bounds__(256)
k_final(float* __restrict__ out) {
    const int tid = threadIdx.x;
    __shared__ float red[8];
    float lp = g_loglam[tid] - g_integ[tid];
    float nv = g_nev[tid];
    float sLP = block_reduce(lp, red);
    __syncthreads();
    float sNV = block_reduce(nv, red);
    if (tid == 0) {
        out[0] = -sLP;
        out[1] = sNV;
    }
}

// ---------------- launch ----------------
extern "C" void kernel_launch(void* const* d_in, const int* in_sizes, int n_in,
                              void* d_out, int out_size) {
    const int*   event = (const int*)  d_in[0];
    const float* dtime = (const float*)d_in[1];
    const float* dur   = (const float*)d_in[2];
    const float* dts   = (const float*)d_in[3];
    // d_in[4] = index_of_hidden_sampling (unused by the reference)
    const float* mask  = (const float*)d_in[5];
    const float* Emb   = (const float*)d_in[6];
    const float* W     = (const float*)d_in[7];
    const float* bias  = (const float*)d_in[8];
    const float* Wl    = (const float*)d_in[9];

    float* out = (float*)d_out;
    long long lam_elems = (long long)HN * 32;
    long long lamoff = (long long)out_size - lam_elems;
    if (lamoff < 0) lamoff = 0;
    float* lam_out = out + lamoff;

    k_prex  <<<NVOC, H7>>>(Emb, W, bias);
    k_scan  <<<BB / 2, H7>>>(event, dtime, W);
    k_sample<<<BB, 256>>>(dts, mask, dur, Wl, lam_out);
    k_target<<<BB, 256>>>(event, Wl);
    k_final <<<1, 256>>>(out);
}

// round 10
// speedup vs baseline: 1.1643x; 1.1643x over previous
#include <cuda_runtime.h>
#include <math.h>

#define BB    256
#define T2V   1026
#define TP1   1025
#define SSV   1024
#define NVOC  35
#define H7    224
#define HN    (BB*SSV)
#define EPSV  2.220446049250313e-16f
#define LOG2E 1.4426950408889634f
#define LN2   0.6931471805599453f
#define FULLM 0xffffffffu

// ---------------- device scratch ----------------
static __device__ float g_prex[NVOC * H7];
static __device__ float g_c [BB * TP1 * 32];
static __device__ float g_cb[BB * TP1 * 32];
static __device__ float g_d [BB * TP1 * 32];   // delta in log2 domain
static __device__ float g_o [BB * TP1 * 32];
static __device__ float g_h [BB * TP1 * 32];
static __device__ float g_loglam[BB], g_nev[BB], g_integ[BB];

// ---------------- fast math ----------------
__device__ __forceinline__ float ex2f(float x){ float r; asm("ex2.approx.f32 %0,%1;":"=f"(r):"f"(x)); return r; }
__device__ __forceinline__ float lg2f(float x){ float r; asm("lg2.approx.f32 %0,%1;":"=f"(r):"f"(x)); return r; }
__device__ __forceinline__ float rcpf(float x){ float r; asm("rcp.approx.f32 %0,%1;":"=f"(r):"f"(x)); return r; }
__device__ __forceinline__ float sig_fast(float x){
    float s = ex2f(-fabsf(x) * LOG2E);
    float r = rcpf(1.0f + s);
    return x >= 0.0f ? r : s * r;
}
__device__ __forceinline__ float tanh_fast(float x){
    float s2 = ex2f(-2.0f * LOG2E * fabsf(x));
    float tv = (1.0f - s2) * rcpf(1.0f + s2);
    return x >= 0.0f ? tv : -tv;
}
__device__ __forceinline__ float softplus_fast(float x){
    return fmaxf(x, 0.0f) + lg2f(1.0f + ex2f(-fabsf(x) * LOG2E)) * LN2;
}
__device__ __forceinline__ float softplus_log2(float x){   // softplus(x)/ln2
    return fmaxf(x, 0.0f) * LOG2E + lg2f(1.0f + ex2f(-fabsf(x) * LOG2E));
}

// block reduction (result valid on thread 0); blockDim = 256
__device__ __forceinline__ float block_reduce(float v, float* sh) {
    #pragma unroll
    for (int o = 16; o > 0; o >>= 1) v += __shfl_down_sync(FULLM, v, o);
    int wid = threadIdx.x >> 5, lid = threadIdx.x & 31;
    if (lid == 0) sh[wid] = v;
    __syncthreads();
    if (wid == 0) {
        v = (lid < 8) ? sh[lid] : 0.0f;
        #pragma unroll
        for (int o = 4; o > 0; o >>= 1) v += __shfl_down_sync(FULLM, v, o);
    }
    return v;
}

// ---------------- kernel A: prex[v][j] = Emb[v]·Wx[:,j] + b[j] -------------
__global__ void k_prex(const float* __restrict__ Emb,
                       const float* __restrict__ W,
                       const float* __restrict__ bias) {
    int v = blockIdx.x;
    int j = threadIdx.x;
    float acc = bias[j];
    #pragma unroll
    for (int k = 0; k < 32; k++)
        acc += Emb[v * 32 + k] * W[k * H7 + j];
    g_prex[v * H7 + j] = acc;
}

// ---------------- kernel B: scan (R2 structure + critical-path trims) ------
// thread j = gate (j>>5) of unit (j&31); uniform activation per warp.
// phase 2 (cell update) on warp 0 only; o/delta stored by warps 3/6 in phase 1;
// decay e precomputed by delta warp in phase 1; ev/dt staged in SMEM.
__global__ void __launch_bounds__(224, 2)
k_scan(const int*   __restrict__ event,
       const float* __restrict__ dtime,
       const float* __restrict__ W) {
    const int b    = blockIdx.x;
    const int j    = threadIdx.x;
    const int w    = j >> 5;
    const int lane = j & 31;

    __shared__ float4 h4s[8];                  // h vector (32 floats)
    __shared__ float  act[H7];
    __shared__ float  e_sh[32];
    __shared__ float  prex_sh[NVOC * H7];      // 31.4 KB
    __shared__ float  dt_sh[T2V];
    __shared__ int    ev_sh[T2V];
    float* h_sh = (float*)h4s;

    const int*   evrow = event + b * T2V;
    const float* dtrow = dtime + b * T2V;
    for (int i = j; i < NVOC * H7; i += H7) prex_sh[i] = g_prex[i];
    for (int i = j; i < T2V; i += H7) { dt_sh[i] = dtrow[i]; ev_sh[i] = evrow[i]; }

    // thread j owns column j of W_h (rows 32..63 of W)
    float wcol[32];
    #pragma unroll
    for (int k = 0; k < 32; k++)
        wcol[k] = W[(32 + k) * H7 + j];

    if (j < 32) h_sh[j] = 0.0f;
    float cm = 0.0f, cbm = 0.0f;               // carries (warp 0)

    float* outc  = g_c  + b * TP1 * 32;
    float* outcb = g_cb + b * TP1 * 32;
    float* outd  = g_d  + b * TP1 * 32;
    float* outo  = g_o  + b * TP1 * 32;
    float* outh  = g_h  + b * TP1 * 32;

    __syncthreads();

    float px = prex_sh[ev_sh[0] * H7 + j];

    for (int t = 0; t < TP1; t++) {
        // ---------- phase 1: pre-activation + gate nonlinearity ------------
        float a0 = px, a1 = 0.f, a2 = 0.f, a3 = 0.f;
        #pragma unroll
        for (int q = 0; q < 8; q++) {
            float4 hv = h4s[q];                // broadcast LDS.128
            a0 = fmaf(hv.x, wcol[4 * q + 0], a0);
            a1 = fmaf(hv.y, wcol[4 * q + 1], a1);
            a2 = fmaf(hv.z, wcol[4 * q + 2], a2);
            a3 = fmaf(hv.w, wcol[4 * q + 3], a3);
        }
        float pre = (a0 + a1) + (a2 + a3);

        float a;
        if (w == 2) {                          // z: tanh (uniform per warp)
            a = tanh_fast(pre);
        } else if (w == 6) {                   // delta: softplus, log2 domain
            a = softplus_log2(pre);
            e_sh[lane] = ex2f(-a * dt_sh[t + 1]);   // decay for THIS step
            outd[t * 32 + lane] = a;           // store off critical path
        } else {                               // i,f,o,ib,fb: sigmoid
            a = sig_fast(pre);
            if (w == 3) outo[t * 32 + lane] = a;
        }
        act[j] = a;

        // prefetch next step's pre-x term (hidden under barrier + phase 2)
        int tn = (t + 1 < TP1) ? t + 1 : t;
        px = prex_sh[ev_sh[tn] * H7 + j];

        __syncthreads();

        // ---------- phase 2: cell update (warp 0 only) ----------------------
        if (w == 0) {
            float iv  = act[lane];
            float fv  = act[32  + lane];
            float zv  = act[64  + lane];
            float ov  = act[96  + lane];
            float ibv = act[128 + lane];
            float fbv = act[160 + lane];
            float e   = e_sh[lane];

            float c  = fmaf(fv,  cm,  iv  * zv);
            float cb = fmaf(fbv, cbm, ibv * zv);
            float cn = fmaf(c - cb, e, cb);
            float h  = ov * tanh_fast(cn);

            int base = t * 32 + lane;
            outc [base] = c;
            outcb[base] = cb;
            outh [base] = h;

            h_sh[lane] = h;
            cm = cn; cbm = cb;
        }
        __syncthreads();
    }
}

// ---------------- kernel C: MC sampling + lambda_sample + integral ---------
__global__ void __launch_bounds__(256)
k_sample(const float* __restrict__ dts,
         const float* __restrict__ mask,
         const float* __restrict__ dur,
         const float* __restrict__ Wl,
         float* __restrict__ lam_out) {
    const int b    = blockIdx.x;
    const int tid  = threadIdx.x;
    const int lane = tid & 31;
    const int wid  = tid >> 5;

    __shared__ float sh_ch[8][32];
    __shared__ float red[8];

    float wle[32];
    const float4* wl4 = (const float4*)(Wl + lane * 32);
    #pragma unroll
    for (int p = 0; p < 8; p++) {
        float4 wv = wl4[p];
        wle[4 * p + 0] = wv.x; wle[4 * p + 1] = wv.y;
        wle[4 * p + 2] = wv.z; wle[4 * p + 3] = wv.w;
    }

    float accLam = 0.0f, accMask = 0.0f;

    for (int s = wid; s < SSV; s += 8) {
        int r    = b * SSV + s;
        int base = r * 32;

        float cv  = g_c [base + lane];
        float cbv = g_cb[base + lane];
        float dv  = g_d [base + lane];    // log2-domain delta
        float ov  = g_o [base + lane];
        float dtv = dts[r];

        float cd  = fmaf(cv - cbv, ex2f(-dv * dtv), cbv);
        float chv = ov * tanh_fast(cd);
        sh_ch[wid][lane] = chv;
        __syncwarp();

        float d0 = 0.f, d1 = 0.f, d2 = 0.f, d3 = 0.f;
        const float4* ch4 = (const float4*)sh_ch[wid];
        #pragma unroll
        for (int p = 0; p < 8; p++) {
            float4 c4 = ch4[p];
            d0 = fmaf(c4.x, wle[4 * p + 0], d0);
            d1 = fmaf(c4.y, wle[4 * p + 1], d1);
            d2 = fmaf(c4.z, wle[4 * p + 2], d2);
            d3 = fmaf(c4.w, wle[4 * p + 3], d3);
        }
        float sp = softplus_fast((d0 + d1) + (d2 + d3));
        lam_out[(size_t)r * 32 + lane] = sp;

        float m = mask[r];
        accLam += sp * m;
        if (lane == 0) accMask += m;
        __syncwarp();
    }

    float sLam = block_reduce(accLam, red);
    __syncthreads();
    float sMask = block_reduce(accMask, red);
    if (tid == 0) g_integ[b] = __fdividef(sLam, sMask) * dur[b];
}

// ---------------- kernel D: target log-lambda ------------------------------
__global__ void __launch_bounds__(256)
k_target(const int* __restrict__ event,
         const float* __restrict__ Wl) {
    const int b   = blockIdx.x;
    const int tid = threadIdx.x;

    __shared__ float wl[32 * 33];              // stride 33: conflict-free
    __shared__ float red[8];
    for (int i = tid; i < 1024; i += 256)
        wl[(i >> 5) * 33 + (i & 31)] = Wl[i];
    __syncthreads();

    const int* evrow = event + b * T2V;
    float accL = 0.0f, accN = 0.0f;

    for (int t = tid; t < TP1; t += 256) {
        int tgt = evrow[t + 1];
        bool m  = (tgt < 32);
        int tt  = m ? tgt : 0;

        const float4* h4 = (const float4*)(g_h + (b * TP1 + t) * 32);
        const float* wr  = wl + tt * 33;
        float d0 = 0.f, d1 = 0.f, d2 = 0.f, d3 = 0.f;
        #pragma unroll
        for (int p = 0; p < 8; p++) {
            float4 hv = h4[p];
            d0 = fmaf(hv.x, wr[4 * p + 0], d0);
            d1 = fmaf(hv.y, wr[4 * p + 1], d1);
            d2 = fmaf(hv.z, wr[4 * p + 2], d2);
            d3 = fmaf(hv.w, wr[4 * p + 3], d3);
        }
        float lam = softplus_fast((d0 + d1) + (d2 + d3));
        if (m) { accL += lg2f(lam + EPSV) * LN2; accN += 1.0f; }
    }

    float sL = block_reduce(accL, red);
    __syncthreads();
    float sN = block_reduce(accN, red);
    if (tid == 0) { g_loglam[b] = sL; g_nev[b] = sN; }
}

// ---------------- kernel E: final scalars ----------------------------------
__global__ void __launch_bounds__(256)
k_final(float* __restrict__ out) {
    const int tid = threadIdx.x;
    __shared__ float red[8];
    float lp = g_loglam[tid] - g_integ[tid];
    float nv = g_nev[tid];
    float sLP = block_reduce(lp, red);
    __syncthreads();
    float sNV = block_reduce(nv, red);
    if (tid == 0) {
        out[0] = -sLP;
        out[1] = sNV;
    }
}

// ---------------- launch ----------------
extern "C" void kernel_launch(void* const* d_in, const int* in_sizes, int n_in,
                              void* d_out, int out_size) {
    const int*   event = (const int*)  d_in[0];
    const float* dtime = (const float*)d_in[1];
    const float* dur   = (const float*)d_in[2];
    const float* dts   = (const float*)d_in[3];
    // d_in[4] = index_of_hidden_sampling (unused by the reference)
    const float* mask  = (const float*)d_in[5];
    const float* Emb   = (const float*)d_in[6];
    const float* W     = (const float*)d_in[7];
    const float* bias  = (const float*)d_in[8];
    const float* Wl    = (const float*)d_in[9];

    float* out = (float*)d_out;
    long long lam_elems = (long long)HN * 32;
    long long lamoff = (long long)out_size - lam_elems;
    if (lamoff < 0) lamoff = 0;
    float* lam_out = out + lamoff;

    k_prex  <<<NVOC, H7>>>(Emb, W, bias);
    k_scan  <<<BB, H7>>>(event, dtime, W);
    k_sample<<<BB, 256>>>(dts, mask, dur, Wl, lam_out);
    k_target<<<BB, 256>>>(event, Wl);
    k_final <<<1, 256>>>(out);
}

// round 11
// speedup vs baseline: 1.3343x; 1.1461x over previous
#include <cuda_runtime.h>
#include <math.h>

#define BB    256
#define T2V   1026
#define TP1   1025
#define NVOC  35
#define H7    224
#define HN    (BB*1024)
#define EPSV  2.220446049250313e-16f
#define LOG2E 1.4426950408889634f
#define LN2   0.6931471805599453f
#define FULLM 0xffffffffu

// ---------------- device scratch (small scalars only) ----------------
static __device__ float g_prex[NVOC * H7];
static __device__ float g_intA[BB], g_intB[BB], g_mskA[BB], g_mskB[BB];
static __device__ float g_loglam[BB], g_nev[BB];

// ---------------- fast math ----------------
__device__ __forceinline__ float ex2f(float x){ float r; asm("ex2.approx.f32 %0,%1;":"=f"(r):"f"(x)); return r; }
__device__ __forceinline__ float lg2f(float x){ float r; asm("lg2.approx.f32 %0,%1;":"=f"(r):"f"(x)); return r; }
__device__ __forceinline__ float rcpf(float x){ float r; asm("rcp.approx.f32 %0,%1;":"=f"(r):"f"(x)); return r; }
__device__ __forceinline__ float sig_fast(float x){
    float s = ex2f(-fabsf(x) * LOG2E);
    float r = rcpf(1.0f + s);
    return x >= 0.0f ? r : s * r;
}
__device__ __forceinline__ float tanh_fast(float x){
    float s2 = ex2f(-2.0f * LOG2E * fabsf(x));
    float tv = (1.0f - s2) * rcpf(1.0f + s2);
    return x >= 0.0f ? tv : -tv;
}
__device__ __forceinline__ float softplus_fast(float x){
    return fmaxf(x, 0.0f) + lg2f(1.0f + ex2f(-fabsf(x) * LOG2E)) * LN2;
}
__device__ __forceinline__ float softplus_log2(float x){   // softplus(x)/ln2
    return fmaxf(x, 0.0f) * LOG2E + lg2f(1.0f + ex2f(-fabsf(x) * LOG2E));
}

// ---------------- SMEM layout (float offsets; float4-aligned blocks) -------
#define OFF_PREX 0        /* 35*224 = 7840 */
#define OFF_RC   7840     /* ring c     64*32 */
#define OFF_RCB  9888     /* ring cbar  64*32 */
#define OFF_RL   11936    /* ring delta 64*32 */
#define OFF_RO   13984    /* ring o     64*32 */
#define OFF_RH   16032    /* ring h     64*32 */
#define OFF_DT   18080    /* dtime row 1026 (+pad) */
#define OFF_EV   19108    /* event row 1026 (int) */
#define OFF_DTS  20136    /* dts row  1025 (+pad) */
#define OFF_MSK  21164    /* mask row 1025 (+pad) */
#define OFF_WLP  22192    /* Wl padded 32*33 */
#define OFF_ACT  23248    /* act 224 */
#define OFF_H    23472    /* h vector 32 */
#define OFF_E    23504    /* decay e 32 */
#define OFF_SHCH 23536    /* per-warp ch transpose 7*32 */
#define OFF_RED  23760    /* reduction 8 */
#define SMEM_FLOATS 23776
#define SMEM_BYTES  (SMEM_FLOATS * 4)

// ---------------- kernel A: prex[v][j] = Emb[v]·Wx[:,j] + b[j] -------------
__global__ void k_prex(const float* __restrict__ Emb,
                       const float* __restrict__ W,
                       const float* __restrict__ bias) {
    int v = blockIdx.x;
    int j = threadIdx.x;
    float acc = bias[j];
    #pragma unroll
    for (int k = 0; k < 32; k++)
        acc += Emb[v * 32 + k] * W[k * H7 + j];
    g_prex[v * H7 + j] = acc;
}

// ---------------- kernel B: fully fused scan + chunked consumers -----------
// Scan core = R10 (proven). Every 64 steps, ALL warps process the last 64
// timesteps' sampling + target rows from the SMEM ring (decoupled from the
// per-step barriers except one extra barrier per chunk).
__global__ void __launch_bounds__(224, 2)
k_scan(const int*   __restrict__ event,
       const float* __restrict__ dtime,
       const float* __restrict__ W,
       const float* __restrict__ Wl,
       const float* __restrict__ dts,
       const float* __restrict__ mask,
       float*       __restrict__ lam_out) {
    extern __shared__ float sm[];
    const int b    = blockIdx.x;
    const int j    = threadIdx.x;
    const int w    = j >> 5;
    const int lane = j & 31;

    float* prex  = sm + OFF_PREX;
    float* ringc = sm + OFF_RC;
    float* ringcb= sm + OFF_RCB;
    float* ringL = sm + OFF_RL;
    float* ringo = sm + OFF_RO;
    float* ringh = sm + OFF_RH;
    float* dt_sh = sm + OFF_DT;
    int*   ev_sh = (int*)(sm + OFF_EV);
    float* dts_sh= sm + OFF_DTS;
    float* msk_sh= sm + OFF_MSK;
    float* wlp   = sm + OFF_WLP;
    float* act   = sm + OFF_ACT;
    float* h_sh  = sm + OFF_H;
    float* e_sh  = sm + OFF_E;
    float* shch  = sm + OFF_SHCH;
    float* red   = sm + OFF_RED;

    const int f0      = b * TP1;
    const int validTp = (HN - f0 < TP1) ? (HN - f0) : TP1;

    // -------- init: stage everything into SMEM once --------
    for (int i = j; i < NVOC * H7; i += H7) prex[i] = g_prex[i];
    for (int i = j; i < T2V; i += H7) {
        dt_sh[i] = dtime[b * T2V + i];
        ev_sh[i] = event[b * T2V + i];
    }
    for (int i = j; i < TP1; i += H7) {
        bool ok = (f0 + i) < HN;
        dts_sh[i] = ok ? dts[f0 + i]  : 0.0f;
        msk_sh[i] = ok ? mask[f0 + i] : 0.0f;
    }
    for (int i = j; i < 1024; i += H7)
        wlp[(i >> 5) * 33 + (i & 31)] = Wl[i];

    // recurrent weight column (rows 32..63 of W)
    float wcol[32];
    #pragma unroll
    for (int k = 0; k < 32; k++)
        wcol[k] = W[(32 + k) * H7 + j];

    // sampler weights: lane e keeps Wl[e][:]
    float wle[32];
    {
        const float4* wl4 = (const float4*)(Wl + lane * 32);
        #pragma unroll
        for (int p = 0; p < 8; p++) {
            float4 wv = wl4[p];
            wle[4*p+0] = wv.x; wle[4*p+1] = wv.y;
            wle[4*p+2] = wv.z; wle[4*p+3] = wv.w;
        }
    }

    if (j < 32) h_sh[j] = 0.0f;
    float cm = 0.0f, cbm = 0.0f;               // carries (warp 0)
    float acc0 = 0.f, acc1 = 0.f, am0 = 0.f, am1 = 0.f;  // integral groups
    float accL = 0.f, accN = 0.f;              // target loglambda

    __syncthreads();

    float px = prex[ev_sh[0] * H7 + j];

    // -------- chunk processor: sampling + target for steps [t0, t0+cnt) ----
    auto chunk = [&](int t0, int cnt) {
        for (int rr = w; rr < cnt; rr += 7) {
            int trow = t0 + rr;
            int base = (trow & 63) * 32 + lane;

            // ---- target log-lambda (all steps) ----
            {
                int tgt = ev_sh[trow + 1];
                bool mm = (tgt < 32);
                int  tt = mm ? tgt : 0;
                float p = ringh[base] * wlp[tt * 33 + lane];
                #pragma unroll
                for (int o = 16; o > 0; o >>= 1) p += __shfl_down_sync(FULLM, p, o);
                if (lane == 0 && mm) {
                    accL += lg2f(softplus_fast(p) + EPSV) * LN2;
                    accN += 1.0f;
                }
            }
            // ---- MC sample row (only valid flat rows) ----
            if (trow < validTp) {
                float c  = ringc [base];
                float cb = ringcb[base];
                float L  = ringL [base];
                float o  = ringo [base];
                float dtv = dts_sh[trow];
                float m   = msk_sh[trow];

                float cd = fmaf(c - cb, ex2f(-L * dtv), cb);
                float ch = o * tanh_fast(cd);
                shch[w * 32 + lane] = ch;
                __syncwarp();

                float d0 = 0.f, d1 = 0.f, d2 = 0.f, d3 = 0.f;
                const float4* c4 = (const float4*)(shch + w * 32);
                #pragma unroll
                for (int p = 0; p < 8; p++) {
                    float4 cv = c4[p];                 // broadcast
                    d0 = fmaf(cv.x, wle[4*p+0], d0);
                    d1 = fmaf(cv.y, wle[4*p+1], d1);
                    d2 = fmaf(cv.z, wle[4*p+2], d2);
                    d3 = fmaf(cv.w, wle[4*p+3], d3);
                }
                float sp = softplus_fast((d0 + d1) + (d2 + d3));
                lam_out[(size_t)(f0 + trow) * 32 + lane] = sp;

                if (b + trow < 1024) { acc0 += sp * m; if (lane == 0) am0 += m; }
                else                 { acc1 += sp * m; if (lane == 0) am1 += m; }
                __syncwarp();
            }
        }
    };

    // ---------------- main scan loop (R10 core) ----------------
    for (int t = 0; t < TP1; t++) {
        if ((t & 63) == 0 && t) {
            chunk(t - 64, 64);
            __syncthreads();     // chunk reads finish before ring overwrite
        }

        // ---------- phase 1: pre-activation + gate nonlinearity ------------
        float a0 = px, a1 = 0.f, a2 = 0.f, a3 = 0.f;
        const float4* h4 = (const float4*)h_sh;
        #pragma unroll
        for (int q = 0; q < 8; q++) {
            float4 hv = h4[q];                 // broadcast LDS.128
            a0 = fmaf(hv.x, wcol[4 * q + 0], a0);
            a1 = fmaf(hv.y, wcol[4 * q + 1], a1);
            a2 = fmaf(hv.z, wcol[4 * q + 2], a2);
            a3 = fmaf(hv.w, wcol[4 * q + 3], a3);
        }
        float pre = (a0 + a1) + (a2 + a3);

        float a;
        int sl = (t & 63) * 32 + lane;
        if (w == 2) {                          // z: tanh (uniform per warp)
            a = tanh_fast(pre);
        } else if (w == 6) {                   // delta: softplus, log2 domain
            a = softplus_log2(pre);
            e_sh[lane] = ex2f(-a * dt_sh[t + 1]);
            ringL[sl] = a;
        } else {                               // i,f,o,ib,fb: sigmoid
            a = sig_fast(pre);
            if (w == 3) ringo[sl] = a;
        }
        act[j] = a;

        // prefetch next step's pre-x term
        int tn = (t + 1 < TP1) ? t + 1 : t;
        px = prex[ev_sh[tn] * H7 + j];

        __syncthreads();

        // ---------- phase 2: cell update (warp 0 only) ----------------------
        if (w == 0) {
            float iv  = act[lane];
            float fv  = act[32  + lane];
            float zv  = act[64  + lane];
            float ov  = act[96  + lane];
            float ibv = act[128 + lane];
            float fbv = act[160 + lane];
            float e   = e_sh[lane];

            float c  = fmaf(fv,  cm,  iv  * zv);
            float cb = fmaf(fbv, cbm, ibv * zv);
            float cn = fmaf(c - cb, e, cb);
            float h  = ov * tanh_fast(cn);

            ringc [sl] = c;
            ringcb[sl] = cb;
            ringh [sl] = h;

            h_sh[lane] = h;
            cm = cn; cbm = cb;
        }
        __syncthreads();
    }

    // tail: step 1024 (1025 = 16*64 + 1)
    chunk(1024, 1);
    __syncthreads();

    // ---------------- epilogue: block reductions (7 warps) -----------------
    auto bred = [&](float v) -> float {
        #pragma unroll
        for (int o = 16; o > 0; o >>= 1) v += __shfl_down_sync(FULLM, v, o);
        if (lane == 0) red[w] = v;
        __syncthreads();
        float r = 0.0f;
        if (j == 0) {
            #pragma unroll
            for (int k = 0; k < 7; k++) r += red[k];
        }
        __syncthreads();
        return r;
    };

    float s;
    s = bred(acc0); if (j == 0) g_intA[b] = s;
    s = bred(acc1); if (j == 0) g_intB[b] = s;
    s = bred(am0);  if (j == 0) g_mskA[b] = s;
    s = bred(am1);  if (j == 0) g_mskB[b] = s;
    s = bred(accL); if (j == 0) g_loglam[b] = s;
    s = bred(accN); if (j == 0) g_nev[b] = s;
}

// ---------------- final: stitch integral groups + reduce scalars ----------
__global__ void __launch_bounds__(256)
k_final(const float* __restrict__ dur, float* __restrict__ out) {
    const int bb = threadIdx.x;     // one thread per group
    __shared__ float red[8];

    float lamsum = g_intA[bb] + (bb > 0 ? g_intB[bb - 1] : 0.0f);
    float msum   = g_mskA[bb] + (bb > 0 ? g_mskB[bb - 1] : 0.0f);
    float integ  = __fdividef(lamsum, msum) * dur[bb];
    float lp = g_loglam[bb] - integ;
    float nv = g_nev[bb];

    int wid = threadIdx.x >> 5, lid = threadIdx.x & 31;
    #pragma unroll
    for (int o = 16; o > 0; o >>= 1) lp += __shfl_down_sync(FULLM, lp, o);
    if (lid == 0) red[wid] = lp;
    __syncthreads();
    if (wid == 0) {
        float v = (lid < 8) ? red[lid] : 0.0f;
        #pragma unroll
        for (int o = 4; o > 0; o >>= 1) v += __shfl_down_sync(FULLM, v, o);
        if (lid == 0) out[0] = -v;
    }
    __syncthreads();
    #pragma unroll
    for (int o = 16; o > 0; o >>= 1) nv += __shfl_down_sync(FULLM, nv, o);
    if (lid == 0) red[wid] = nv;
    __syncthreads();
    if (wid == 0) {
        float v = (lid < 8) ? red[lid] : 0.0f;
        #pragma unroll
        for (int o = 4; o > 0; o >>= 1) v += __shfl_down_sync(FULLM, v, o);
        if (lid == 0) out[1] = v;
    }
}

// ---------------- launch ----------------
extern "C" void kernel_launch(void* const* d_in, const int* in_sizes, int n_in,
                              void* d_out, int out_size) {
    const int*   event = (const int*)  d_in[0];
    const float* dtime = (const float*)d_in[1];
    const float* dur   = (const float*)d_in[2];
    const float* dts   = (const float*)d_in[3];
    // d_in[4] = index_of_hidden_sampling (unused by the reference)
    const float* mask  = (const float*)d_in[5];
    const float* Emb   = (const float*)d_in[6];
    const float* W     = (const float*)d_in[7];
    const float* bias  = (const float*)d_in[8];
    const float* Wl    = (const float*)d_in[9];

    float* out = (float*)d_out;
    long long lam_elems = (long long)HN * 32;
    long long lamoff = (long long)out_size - lam_elems;
    if (lamoff < 0) lamoff = 0;
    float* lam_out = out + lamoff;

    static int attr_set = 0;
    if (!attr_set) {
        cudaFuncSetAttribute(k_scan, cudaFuncAttributeMaxDynamicSharedMemorySize,
                             SMEM_BYTES);
        attr_set = 1;
    }

    k_prex <<<NVOC, H7>>>(Emb, W, bias);
    k_scan <<<BB, H7, SMEM_BYTES>>>(event, dtime, W, Wl, dts, mask, lam_out);
    k_final<<<1, 256>>>(dur, out);
}

// round 12
// speedup vs baseline: 1.3995x; 1.0489x over previous
#include <cuda_runtime.h>
#include <math.h>

#define BB    256
#define T2V   1026
#define TP1   1025
#define NVOC  35
#define H7    224
#define HN    (BB*1024)
#define EPSV  2.220446049250313e-16f
#define LOG2E 1.4426950408889634f
#define LN2   0.6931471805599453f
#define FULLM 0xffffffffu

// ---------------- device scratch (small scalars only) ----------------
static __device__ float g_prex[NVOC * H7];
static __device__ float g_intA[BB], g_intB[BB], g_mskA[BB], g_mskB[BB];
static __device__ float g_loglam[BB], g_nev[BB];

// ---------------- fast math ----------------
__device__ __forceinline__ float ex2f(float x){ float r; asm("ex2.approx.f32 %0,%1;":"=f"(r):"f"(x)); return r; }
__device__ __forceinline__ float lg2f(float x){ float r; asm("lg2.approx.f32 %0,%1;":"=f"(r):"f"(x)); return r; }
__device__ __forceinline__ float rcpf(float x){ float r; asm("rcp.approx.f32 %0,%1;":"=f"(r):"f"(x)); return r; }
__device__ __forceinline__ float sig_fast(float x){
    float s = ex2f(-fabsf(x) * LOG2E);
    float r = rcpf(1.0f + s);
    return x >= 0.0f ? r : s * r;
}
__device__ __forceinline__ float tanh_fast(float x){
    float s2 = ex2f(-2.0f * LOG2E * fabsf(x));
    float tv = (1.0f - s2) * rcpf(1.0f + s2);
    return x >= 0.0f ? tv : -tv;
}
__device__ __forceinline__ float softplus_fast(float x){
    return fmaxf(x, 0.0f) + lg2f(1.0f + ex2f(-fabsf(x) * LOG2E)) * LN2;
}
__device__ __forceinline__ float softplus_log2(float x){   // softplus(x)/ln2
    return fmaxf(x, 0.0f) * LOG2E + lg2f(1.0f + ex2f(-fabsf(x) * LOG2E));
}
__device__ __forceinline__ unsigned su32(const void* p){
    unsigned a;
    asm("{ .reg .u64 t; cvta.to.shared.u64 t, %1; cvt.u32.u64 %0, t; }" : "=r"(a) : "l"(p));
    return a;
}

// ---------------- SMEM layout (float offsets; 16B-aligned blocks) ----------
#define OFF_PREX 0        /* 35*224 = 7840 */
#define OFF_RC   7840     /* ring c     64*32 */
#define OFF_RCB  9888     /* ring cbar  64*32 */
#define OFF_RL   11936    /* ring delta 64*32 */
#define OFF_RO   13984    /* ring o     64*32 */
#define OFF_RH   16032    /* ring h     64*32 */
#define OFF_DT   18080    /* dtime row 1026 (+pad) */
#define OFF_EV   19108    /* event row 1026 (int) */
#define OFF_DTS  20136    /* dts row  1025 (+pad) */
#define OFF_MSK  21164    /* mask row 1025 (+pad) */
#define OFF_WLP  22192    /* Wl padded 32*33 */
#define OFF_ACT  23248    /* act 224 */
#define OFF_H    23472    /* h vector 32 */
#define OFF_E    23504    /* decay e 32 */
#define OFF_SHCH 23536    /* per-warp ch transpose 7*32 */
#define OFF_RED  23760    /* reduction 8 */
#define SMEM_FLOATS 23776
#define SMEM_BYTES  (SMEM_FLOATS * 4)

// ---------------- kernel A: prex[v][j] = Emb[v]·Wx[:,j] + b[j] -------------
__global__ void k_prex(const float* __restrict__ Emb,
                       const float* __restrict__ W,
                       const float* __restrict__ bias) {
    int v = blockIdx.x;
    int j = threadIdx.x;
    float acc = bias[j];
    #pragma unroll
    for (int k = 0; k < 32; k++)
        acc += Emb[v * 32 + k] * W[k * H7 + j];
    g_prex[v * H7 + j] = acc;
}

// ---------------- kernel B: fused scan + chunked consumers (R11) -----------
// Phase-1 dot now uses packed fma.rn.f32x2: 16 FMA2 instead of 32 FFMA.
__global__ void __launch_bounds__(224, 2)
k_scan(const int*   __restrict__ event,
       const float* __restrict__ dtime,
       const float* __restrict__ W,
       const float* __restrict__ Wl,
       const float* __restrict__ dts,
       const float* __restrict__ mask,
       float*       __restrict__ lam_out) {
    extern __shared__ float sm[];
    const int b    = blockIdx.x;
    const int j    = threadIdx.x;
    const int w    = j >> 5;
    const int lane = j & 31;

    float* prex  = sm + OFF_PREX;
    float* ringc = sm + OFF_RC;
    float* ringcb= sm + OFF_RCB;
    float* ringL = sm + OFF_RL;
    float* ringo = sm + OFF_RO;
    float* ringh = sm + OFF_RH;
    float* dt_sh = sm + OFF_DT;
    int*   ev_sh = (int*)(sm + OFF_EV);
    float* dts_sh= sm + OFF_DTS;
    float* msk_sh= sm + OFF_MSK;
    float* wlp   = sm + OFF_WLP;
    float* act   = sm + OFF_ACT;
    float* h_sh  = sm + OFF_H;
    float* e_sh  = sm + OFF_E;
    float* shch  = sm + OFF_SHCH;
    float* red   = sm + OFF_RED;

    const int f0      = b * TP1;
    const int validTp = (HN - f0 < TP1) ? (HN - f0) : TP1;

    // -------- init: stage everything into SMEM once --------
    for (int i = j; i < NVOC * H7; i += H7) prex[i] = g_prex[i];
    for (int i = j; i < T2V; i += H7) {
        dt_sh[i] = dtime[b * T2V + i];
        ev_sh[i] = event[b * T2V + i];
    }
    for (int i = j; i < TP1; i += H7) {
        bool ok = (f0 + i) < HN;
        dts_sh[i] = ok ? dts[f0 + i]  : 0.0f;
        msk_sh[i] = ok ? mask[f0 + i] : 0.0f;
    }
    for (int i = j; i < 1024; i += H7)
        wlp[(i >> 5) * 33 + (i & 31)] = Wl[i];

    // packed recurrent weight column: wp[k] = (W_h[2k][j], W_h[2k+1][j])
    unsigned long long wp[16];
    #pragma unroll
    for (int k = 0; k < 16; k++) {
        float wlo = W[(32 + 2 * k)     * H7 + j];
        float whi = W[(32 + 2 * k + 1) * H7 + j];
        asm("mov.b64 %0, {%1,%2};" : "=l"(wp[k]) : "f"(wlo), "f"(whi));
    }

    // sampler weights: lane e keeps Wl[e][:]
    float wle[32];
    {
        const float4* wl4 = (const float4*)(Wl + lane * 32);
        #pragma unroll
        for (int p = 0; p < 8; p++) {
            float4 wv = wl4[p];
            wle[4*p+0] = wv.x; wle[4*p+1] = wv.y;
            wle[4*p+2] = wv.z; wle[4*p+3] = wv.w;
        }
    }

    if (j < 32) h_sh[j] = 0.0f;
    float cm = 0.0f, cbm = 0.0f;               // carries (warp 0)
    float acc0 = 0.f, acc1 = 0.f, am0 = 0.f, am1 = 0.f;  // integral groups
    float accL = 0.f, accN = 0.f;              // target loglambda

    const unsigned hb = su32(h_sh);

    __syncthreads();

    float px = prex[ev_sh[0] * H7 + j];

    // -------- chunk processor: sampling + target for steps [t0, t0+cnt) ----
    auto chunk = [&](int t0, int cnt) {
        for (int rr = w; rr < cnt; rr += 7) {
            int trow = t0 + rr;
            int base = (trow & 63) * 32 + lane;

            // ---- target log-lambda (all steps) ----
            {
                int tgt = ev_sh[trow + 1];
                bool mm = (tgt < 32);
                int  tt = mm ? tgt : 0;
                float p = ringh[base] * wlp[tt * 33 + lane];
                #pragma unroll
                for (int o = 16; o > 0; o >>= 1) p += __shfl_down_sync(FULLM, p, o);
                if (lane == 0 && mm) {
                    accL += lg2f(softplus_fast(p) + EPSV) * LN2;
                    accN += 1.0f;
                }
            }
            // ---- MC sample row (only valid flat rows) ----
            if (trow < validTp) {
                float c  = ringc [base];
                float cb = ringcb[base];
                float L  = ringL [base];
                float o  = ringo [base];
                float dtv = dts_sh[trow];
                float m   = msk_sh[trow];

                float cd = fmaf(c - cb, ex2f(-L * dtv), cb);
                float ch = o * tanh_fast(cd);
                shch[w * 32 + lane] = ch;
                __syncwarp();

                float d0 = 0.f, d1 = 0.f, d2 = 0.f, d3 = 0.f;
                const float4* c4 = (const float4*)(shch + w * 32);
                #pragma unroll
                for (int p = 0; p < 8; p++) {
                    float4 cv = c4[p];                 // broadcast
                    d0 = fmaf(cv.x, wle[4*p+0], d0);
                    d1 = fmaf(cv.y, wle[4*p+1], d1);
                    d2 = fmaf(cv.z, wle[4*p+2], d2);
                    d3 = fmaf(cv.w, wle[4*p+3], d3);
                }
                float sp = softplus_fast((d0 + d1) + (d2 + d3));
                lam_out[(size_t)(f0 + trow) * 32 + lane] = sp;

                if (b + trow < 1024) { acc0 += sp * m; if (lane == 0) am0 += m; }
                else                 { acc1 += sp * m; if (lane == 0) am1 += m; }
                __syncwarp();
            }
        }
    };

    // ---------------- main scan loop ----------------
    for (int t = 0; t < TP1; t++) {
        if ((t & 63) == 0 && t) {
            chunk(t - 64, 64);
            __syncthreads();     // chunk reads finish before ring overwrite
        }

        // ---------- phase 1: packed-f32x2 dot + gate nonlinearity ----------
        unsigned long long pacc0, pacc1, pacc2, pacc3;
        asm("mov.b64 %0, {%1,%2};" : "=l"(pacc0) : "f"(px), "f"(0.0f));
        asm("mov.b64 %0, 0;" : "=l"(pacc1));
        asm("mov.b64 %0, 0;" : "=l"(pacc2));
        asm("mov.b64 %0, 0;" : "=l"(pacc3));
        #pragma unroll
        for (int q = 0; q < 4; q++) {
            unsigned long long hA, hB, hC, hD;
            asm volatile("ld.shared.v2.b64 {%0,%1},[%2];" : "=l"(hA), "=l"(hB) : "r"(hb + 32 * q));
            asm volatile("ld.shared.v2.b64 {%0,%1},[%2];" : "=l"(hC), "=l"(hD) : "r"(hb + 32 * q + 16));
            asm("fma.rn.f32x2 %0,%1,%2,%0;" : "+l"(pacc0) : "l"(hA), "l"(wp[4*q+0]));
            asm("fma.rn.f32x2 %0,%1,%2,%0;" : "+l"(pacc1) : "l"(hB), "l"(wp[4*q+1]));
            asm("fma.rn.f32x2 %0,%1,%2,%0;" : "+l"(pacc2) : "l"(hC), "l"(wp[4*q+2]));
            asm("fma.rn.f32x2 %0,%1,%2,%0;" : "+l"(pacc3) : "l"(hD), "l"(wp[4*q+3]));
        }
        asm("add.rn.f32x2 %0,%0,%1;" : "+l"(pacc0) : "l"(pacc1));
        asm("add.rn.f32x2 %0,%0,%1;" : "+l"(pacc2) : "l"(pacc3));
        asm("add.rn.f32x2 %0,%0,%1;" : "+l"(pacc0) : "l"(pacc2));
        float plo, phi;
        asm("mov.b64 {%0,%1},%2;" : "=f"(plo), "=f"(phi) : "l"(pacc0));
        float pre = plo + phi;

        float a;
        int sl = (t & 63) * 32 + lane;
        if (w == 2) {                          // z: tanh (uniform per warp)
            a = tanh_fast(pre);
        } else if (w == 6) {                   // delta: softplus, log2 domain
            a = softplus_log2(pre);
            e_sh[lane] = ex2f(-a * dt_sh[t + 1]);
            ringL[sl] = a;
        } else {                               // i,f,o,ib,fb: sigmoid
            a = sig_fast(pre);
            if (w == 3) ringo[sl] = a;
        }
        act[j] = a;

        // prefetch next step's pre-x term
        int tn = (t + 1 < TP1) ? t + 1 : t;
        px = prex[ev_sh[tn] * H7 + j];

        __syncthreads();

        // ---------- phase 2: cell update (warp 0 only) ----------------------
        if (w == 0) {
            float iv  = act[lane];
            float fv  = act[32  + lane];
            float zv  = act[64  + lane];
            float ov  = act[96  + lane];
            float ibv = act[128 + lane];
            float fbv = act[160 + lane];
            float e   = e_sh[lane];

            float c  = fmaf(fv,  cm,  iv  * zv);
            float cb = fmaf(fbv, cbm, ibv * zv);
            float cn = fmaf(c - cb, e, cb);
            float h  = ov * tanh_fast(cn);

            ringc [sl] = c;
            ringcb[sl] = cb;
            ringh [sl] = h;

            h_sh[lane] = h;
            cm = cn; cbm = cb;
        }
        __syncthreads();
    }

    // tail: step 1024 (1025 = 16*64 + 1)
    chunk(1024, 1);
    __syncthreads();

    // ---------------- epilogue: block reductions (7 warps) -----------------
    auto bred = [&](float v) -> float {
        #pragma unroll
        for (int o = 16; o > 0; o >>= 1) v += __shfl_down_sync(FULLM, v, o);
        if (lane == 0) red[w] = v;
        __syncthreads();
        float r = 0.0f;
        if (j == 0) {
            #pragma unroll
            for (int k = 0; k < 7; k++) r += red[k];
        }
        __syncthreads();
        return r;
    };

    float s;
    s = bred(acc0); if (j == 0) g_intA[b] = s;
    s = bred(acc1); if (j == 0) g_intB[b] = s;
    s = bred(am0);  if (j == 0) g_mskA[b] = s;
    s = bred(am1);  if (j == 0) g_mskB[b] = s;
    s = bred(accL); if (j == 0) g_loglam[b] = s;
    s = bred(accN); if (j == 0) g_nev[b] = s;
}

// ---------------- final: stitch integral groups + reduce scalars ----------
__global__ void __launch_bounds__(256)
k_final(const float* __restrict__ dur, float* __restrict__ out) {
    const int bb = threadIdx.x;     // one thread per group
    __shared__ float red[8];

    float lamsum = g_intA[bb] + (bb > 0 ? g_intB[bb - 1] : 0.0f);
    float msum   = g_mskA[bb] + (bb > 0 ? g_mskB[bb - 1] : 0.0f);
    float integ  = __fdividef(lamsum, msum) * dur[bb];
    float lp = g_loglam[bb] - integ;
    float nv = g_nev[bb];

    int wid = threadIdx.x >> 5, lid = threadIdx.x & 31;
    #pragma unroll
    for (int o = 16; o > 0; o >>= 1) lp += __shfl_down_sync(FULLM, lp, o);
    if (lid == 0) red[wid] = lp;
    __syncthreads();
    if (wid == 0) {
        float v = (lid < 8) ? red[lid] : 0.0f;
        #pragma unroll
        for (int o = 4; o > 0; o >>= 1) v += __shfl_down_sync(FULLM, v, o);
        if (lid == 0) out[0] = -v;
    }
    __syncthreads();
    #pragma unroll
    for (int o = 16; o > 0; o >>= 1) nv += __shfl_down_sync(FULLM, nv, o);
    if (lid == 0) red[wid] = nv;
    __syncthreads();
    if (wid == 0) {
        float v = (lid < 8) ? red[lid] : 0.0f;
        #pragma unroll
        for (int o = 4; o > 0; o >>= 1) v += __shfl_down_sync(FULLM, v, o);
        if (lid == 0) out[1] = v;
    }
}

// ---------------- launch ----------------
extern "C" void kernel_launch(void* const* d_in, const int* in_sizes, int n_in,
                              void* d_out, int out_size) {
    const int*   event = (const int*)  d_in[0];
    const float* dtime = (const float*)d_in[1];
    const float* dur   = (const float*)d_in[2];
    const float* dts   = (const float*)d_in[3];
    // d_in[4] = index_of_hidden_sampling (unused by the reference)
    const float* mask  = (const float*)d_in[5];
    const float* Emb   = (const float*)d_in[6];
    const float* W     = (const float*)d_in[7];
    const float* bias  = (const float*)d_in[8];
    const float* Wl    = (const float*)d_in[9];

    float* out = (float*)d_out;
    long long lam_elems = (long long)HN * 32;
    long long lamoff = (long long)out_size - lam_elems;
    if (lamoff < 0) lamoff = 0;
    float* lam_out = out + lamoff;

    static int attr_set = 0;
    if (!attr_set) {
        cudaFuncSetAttribute(k_scan, cudaFuncAttributeMaxDynamicSharedMemorySize,
                             SMEM_BYTES);
        attr_set = 1;
    }

    k_prex <<<NVOC, H7>>>(Emb, W, bias);
    k_scan <<<BB, H7, SMEM_BYTES>>>(event, dtime, W, Wl, dts, mask, lam_out);
    k_final<<<1, 256>>>(dur, out);
}